// round 15
// baseline (speedup 1.0000x reference)
#include <cuda_runtime.h>
#include <cuda_fp16.h>
#include <cstdint>

// GINEdgeLayer via split-GEMM on fp16 mma.sync (m16n8k16, fp32 accum),
// all weights SMEM-resident, near-barrier-free main loops.
//   P = H@W1a + b1 per-node (stored fp16, pre-permuted to X1 layout);
//   edge: X1 = relu(P[src] + EA@W1b); agg[dst] += X1@W2 + b2;
//   node: out = MLP2(agg).
//
// R14: P stored fp16 in X1-format rows; edge kernel gathers P[src] rows via
// cp.async directly into the X1 smem buffer as its FIRST async group -> the
// gather latency is fully overlapped with weight loads + stage-1 MMAs, and
// the stage-1 epilogue becomes a pure smem RMW. P traffic halves.
//
// Launch order (ncu capture = index 3 = fused edge kernel):
//   0: init_agg   1: cvt_all   2: P-gemm (MODE 0)   3: edge (MODE 1)   4: node (MODE 2)

static constexpr int N_NODES  = 20000;
static constexpr int N_EDGES  = 200000;
static constexpr int DIM      = 128;
static constexpr int EDGE_DIM = 64;
static constexpr int HID      = 256;

// ---- scratch (__device__ globals; no runtime allocation allowed) ----
__device__ float g_agg[(size_t)N_NODES * DIM];
__device__ __align__(16) __half g_P[(size_t)N_NODES * HID];   // 10.2 MB, permuted fp16
__device__ __align__(16) __half g_W1ap[8 * 128 * 32];  // [2nh*4kc][col][32] fp16 permuted
__device__ __align__(16) __half g_W1bp[4 * 128 * 32];  // [2nh*2kc][col][32]
__device__ __align__(16) __half g_W2p [8 * 128 * 32];  // [8kc][col][32]
__device__ __align__(16) __half g_W3p [8 * 128 * 32];
__device__ __align__(16) __half g_W4p [8 * 128 * 32];

static inline int cdiv(int a, int b) { return (a + b - 1) / b; }

__device__ __forceinline__ uint32_t smem_u32(const void* p) {
    uint32_t a;
    asm("{ .reg .u64 t; cvta.to.shared.u64 t, %1; cvt.u32.u64 %0, t; }" : "=r"(a) : "l"(p));
    return a;
}
// k-permutation for m16n8k16 fp16 fragments (one LDS.128 per row per 32-k chunk)
__device__ __forceinline__ int pos16(int w) {        // bijection on 0..31
    int s = w >> 4, r = w & 15;
    return ((r & 7) >> 1) * 8 + s * 4 + (r >> 3) * 2 + (r & 1);
}

__global__ __launch_bounds__(256)
void init_agg_kernel(const float* __restrict__ H, const float* __restrict__ eps) {
    int i = blockIdx.x * 256 + threadIdx.x;
    if (i < N_NODES * DIM) g_agg[i] = (1.0f + eps[0]) * H[i];
}

__device__ __forceinline__ void perm_write_h(const float* __restrict__ W,
                                             __half* __restrict__ P,
                                             int K, int N, int idx) {
    int k = idx / N, n = idx - k * N;
    int chunk = (n >> 7) * (K >> 5) + (k >> 5);
    P[(size_t)(chunk * 128 + (n & 127)) * 32 + pos16(k & 31)] = __float2half_rn(W[idx]);
}

__global__ __launch_bounds__(256)
void cvt_all_kernel(const float* __restrict__ mW1, const float* __restrict__ mW2,
                    const float* __restrict__ sW1, const float* __restrict__ sW2,
                    __half* __restrict__ W1ap, __half* __restrict__ W1bp,
                    __half* __restrict__ W2p,  __half* __restrict__ W3p,
                    __half* __restrict__ W4p) {
    int i = blockIdx.x * 256 + threadIdx.x;
    if (i < 32768)        perm_write_h(mW1, W1ap, 128, 256, i);
    else if (i < 49152) { // W1b: rows 128..191 of mW1, K=64, N=256
        int l = i - 32768;
        int k = l >> 8, n = l & 255;
        int chunk = (n >> 7) * 2 + (k >> 5);
        W1bp[(size_t)(chunk * 128 + (n & 127)) * 32 + pos16(k & 31)] =
            __float2half_rn(mW1[i]);
    }
    else if (i < 81920)   perm_write_h(mW2, W2p, 256, 128, i - 49152);
    else if (i < 114688)  perm_write_h(sW1, W3p, 128, 256, i - 81920);
    else if (i < 147456)  perm_write_h(sW2, W4p, 256, 128, i - 114688);
}

// =====================================================================
// Unified kernel, CTA tile = 128 rows, 512 threads (16 warps, 4M x 4N,
// warp tile 32x32), fp16 MMA, fp32 accumulate. Weights SMEM-resident.
// MODE 0 (P):    P = H@W1a + b1 -> fp16 permuted rows [., 512B]
// MODE 1 (EDGE): X1 = relu(P[src] + EA@W1b); agg[dst] += X1@W2 + b2
//                (P gathered by cp.async directly into X1 smem)
// MODE 2 (NODE): out = MLP2(agg)
// =====================================================================
template<int MODE>
__global__ void __launch_bounds__(512, 1)
fused_mlp(const float* __restrict__ Ain,
          const __half* __restrict__ W1g, const float* __restrict__ b1,
          const __half* __restrict__ W2g, const float* __restrict__ b2,
          const __half* __restrict__ Pg,
          float*       __restrict__ Cout,
          const int*   __restrict__ srcv, const int* __restrict__ dstv,
          int M)
{
    constexpr bool EDGE = (MODE == 1);
    constexpr int  ROWB = 64;                  // A/B row stride bytes (32 halves)
    constexpr int  XSTB = 576;                 // X1 row stride bytes (conflict-free)
    constexpr int  CHUNKB = 128 * ROWB;        // 8192
    constexpr int  ABYTES = (MODE == 0) ? 4 * CHUNKB : 2 * CHUNKB;
    constexpr int  W1BYTES = EDGE ? 32768 : 65536;
    constexpr int  OFF_A  = 1024;
    constexpr int  OFF_W1 = OFF_A + ABYTES;
    constexpr int  OFF_W2 = OFF_W1 + W1BYTES;
    constexpr int  OFF_X  = OFF_W2 + ((MODE == 0) ? 0 : 65536);
    // MODE0 total: 99328   MODE1: 189440   MODE2: 222208

    extern __shared__ char smem[];
    int*  dstIdx = (int*)(smem + 512);
    char* As  = smem + OFF_A;
    char* W1s = smem + OFF_W1;
    char* W2s = smem + OFF_W2;
    char* X1  = smem + OFF_X;

    const int tid  = threadIdx.x;
    const int lane = tid & 31;
    const int g    = lane >> 2, t = lane & 3;
    const int wid  = tid >> 5;
    const int wm   = wid & 3, wn = wid >> 2;      // 4M x 4N warp grid
    const int m0   = blockIdx.x * 128;

    // ---- EDGE: gather P[src] rows (fp16 permuted, 512 B) into X1 smem ----
    // Issued FIRST (cp.async group 0) so the scattered-row latency overlaps
    // the weight loads and stage-1 compute.
    if constexpr (EDGE) {
        int gr = m0 + (tid >> 2); if (gr >= M) gr = M - 1;
        int srow = srcv[gr];
        uint32_t xd = smem_u32(X1) + (uint32_t)(tid >> 2) * XSTB + (tid & 3) * 128;
        const char* ps = (const char*)Pg + (size_t)srow * 512 + (tid & 3) * 128;
#pragma unroll
        for (int j = 0; j < 8; j++)
            asm volatile("cp.async.cg.shared.global [%0], [%1], 16;"
                         :: "r"(xd + j * 16), "l"(ps + j * 16) : "memory");
        asm volatile("cp.async.commit_group;" ::: "memory");

        if (tid < 128) {
            int gm = m0 + tid;
            dstIdx[tid] = dstv[gm < M ? gm : M - 1];
        }
    }

    // ---- A staging: thread (row=tid/4, aq=tid&3), 8 consecutive k ----
    const int ar = tid >> 2, aq = tid & 3;
    int agm = m0 + ar; if (agm >= M) agm = M - 1;
    const int csub = (aq >> 1) * 2 + (aq & 1);

    auto lda = [&](const float* base, int K, int kc, float4* v) {
        const float* s = base + (size_t)agm * K + kc * 32 + aq * 8;
        v[0] = *reinterpret_cast<const float4*>(s);
        v[1] = *reinterpret_cast<const float4*>(s + 4);
    };
    auto sta = [&](char* buf, const float4* v) {  // fp16 permuted: 4x STS.32
        const float f[8] = { v[0].x, v[0].y, v[0].z, v[0].w,
                             v[1].x, v[1].y, v[1].z, v[1].w };
        uint32_t* d = (uint32_t*)(buf + ar * ROWB);
#pragma unroll
        for (int i = 0; i < 4; i++) {
            __half2 hh = __floats2half2_rn(f[2 * i], f[2 * i + 1]);
            d[i * 4 + csub] = *reinterpret_cast<uint32_t*>(&hh);
        }
    };

    // ---- bulk weight load into resident SMEM (one commit group) ----
    auto ldw = [&](const __half* srcW, char* dst, int bytes) {
        uint32_t d = smem_u32(dst);
        const char* s = (const char*)srcW;
#pragma unroll
        for (int off = tid * 16; off < bytes; off += 512 * 16)
            asm volatile("cp.async.cg.shared.global [%0], [%1], 16;"
                         :: "r"(d + off), "l"(s + off) : "memory");
        asm volatile("cp.async.commit_group;" ::: "memory");
    };

    auto zacc = [&](float (&acc)[2][4][4]) {
#pragma unroll
        for (int mi = 0; mi < 2; mi++)
#pragma unroll
            for (int ni = 0; ni < 4; ni++)
#pragma unroll
                for (int r = 0; r < 4; r++) acc[mi][ni][r] = 0.0f;
    };

    // fragment compute core: 8x LDS.128 + 16 MMA per warp per 32-k chunk
    auto mma_chunk = [&](float (&acc)[2][4][4], const char* abase, int astB,
                         const char* bbase) {
        uint4 a[2][2];
#pragma unroll
        for (int mi = 0; mi < 2; mi++)
#pragma unroll
            for (int rs = 0; rs < 2; rs++)
                a[mi][rs] = *reinterpret_cast<const uint4*>(
                    abase + (size_t)(mi * 16 + rs * 8 + g) * astB + t * 16);
        uint4 b[4];
#pragma unroll
        for (int ni = 0; ni < 4; ni++)
            b[ni] = *reinterpret_cast<const uint4*>(
                bbase + (size_t)(wn * 32 + ni * 8 + g) * ROWB + t * 16);
#pragma unroll
        for (int s = 0; s < 2; s++)
#pragma unroll
            for (int ni = 0; ni < 4; ni++) {
                uint32_t b0 = s ? b[ni].z : b[ni].x;
                uint32_t b1r = s ? b[ni].w : b[ni].y;
#pragma unroll
                for (int mi = 0; mi < 2; mi++) {
                    uint32_t a0 = s ? a[mi][0].z : a[mi][0].x;
                    uint32_t a1 = s ? a[mi][1].z : a[mi][1].x;
                    uint32_t a2 = s ? a[mi][0].w : a[mi][0].y;
                    uint32_t a3 = s ? a[mi][1].w : a[mi][1].y;
                    asm volatile(
                        "mma.sync.aligned.m16n8k16.row.col.f32.f16.f16.f32 "
                        "{%0,%1,%2,%3}, {%4,%5,%6,%7}, {%8,%9}, {%0,%1,%2,%3};"
                        : "+f"(acc[mi][ni][0]), "+f"(acc[mi][ni][1]),
                          "+f"(acc[mi][ni][2]), "+f"(acc[mi][ni][3])
                        : "r"(a0), "r"(a1), "r"(a2), "r"(a3), "r"(b0), "r"(b1r));
                }
            }
    };

    // ---- stage-1 epilogue (per N-half) ----
    auto epilogue1 = [&](float (&acc)[2][4][4], int nh) {
        if constexpr (MODE == 0) {               // P: fp16 permuted rows to gmem
            float2 bv[4];
#pragma unroll
            for (int ni = 0; ni < 4; ni++)
                bv[ni] = *reinterpret_cast<const float2*>(b1 + nh * 128 + wn * 32 + ni * 8 + 2 * t);
#pragma unroll
            for (int mi = 0; mi < 2; mi++)
#pragma unroll
                for (int half = 0; half < 2; half++) {
                    const int row_l = wm * 32 + mi * 16 + g + half * 8;
                    const int gm = m0 + row_l;
                    if (gm < M) {
                        uint32_t pk[4];
#pragma unroll
                        for (int ni = 0; ni < 4; ni++) {
                            __half2 hh = __floats2half2_rn(
                                acc[mi][ni][half * 2 + 0] + bv[ni].x,
                                acc[mi][ni][half * 2 + 1] + bv[ni].y);
                            pk[ni] = *reinterpret_cast<uint32_t*>(&hh);
                        }
                        uint32_t* po = (uint32_t*)Cout + (size_t)gm * 128
                                     + (nh * 4 + wn) * 16 + t * 4;
                        *reinterpret_cast<uint4*>(po) =
                            make_uint4(pk[0], pk[1], pk[2], pk[3]);
                    }
                }
        } else {                                  // relu(P/bias + acc) -> X1 smem
            float2 bv[4];
            if (!EDGE) {
#pragma unroll
                for (int ni = 0; ni < 4; ni++)
                    bv[ni] = *reinterpret_cast<const float2*>(b1 + nh * 128 + wn * 32 + ni * 8 + 2 * t);
            }
#pragma unroll
            for (int mi = 0; mi < 2; mi++)
#pragma unroll
                for (int half = 0; half < 2; half++) {
                    const int row_l = wm * 32 + mi * 16 + g + half * 8;
                    uint32_t* xp = (uint32_t*)(X1 + (size_t)row_l * XSTB)
                                 + (nh * 4 + wn) * 16 + t * 4;
#pragma unroll
                    for (int ni = 0; ni < 4; ni++) {
                        float ax, ay;
                        if (EDGE) {               // gathered P already in X1 slot
                            uint32_t pv = xp[ni];
                            float2 pf = __half22float2(*reinterpret_cast<__half2*>(&pv));
                            ax = pf.x; ay = pf.y;
                        } else { ax = bv[ni].x; ay = bv[ni].y; }
                        float x = fmaxf(acc[mi][ni][half * 2 + 0] + ax, 0.0f);
                        float y = fmaxf(acc[mi][ni][half * 2 + 1] + ay, 0.0f);
                        __half2 hh = __floats2half2_rn(x, y);
                        xp[ni] = *reinterpret_cast<uint32_t*>(&hh);
                    }
                }
        }
    };

    float acc[2][4][4];
    float4 av[2];

    // ================= MODE 0: P-GEMM, fully resident, 1 barrier =================
    if constexpr (MODE == 0) {
        ldw(W1g, W1s, 65536);
#pragma unroll
        for (int kc = 0; kc < 4; kc++) { lda(Ain, 128, kc, av); sta(As + kc * CHUNKB, av); }
        asm volatile("cp.async.wait_group 0;" ::: "memory");
        __syncthreads();
#pragma unroll 1
        for (int nh = 0; nh < 2; nh++) {
            zacc(acc);
#pragma unroll
            for (int kc = 0; kc < 4; kc++)
                mma_chunk(acc, As + kc * CHUNKB + wm * 32 * ROWB, ROWB,
                          W1s + (size_t)(nh * 4 + kc) * CHUNKB);
            epilogue1(acc, nh);
        }
        return;
    }

    // ================= MODE 1: edge =================
    if constexpr (MODE == 1) {
        ldw(W1g, W1s, 32768);                  // W1b (group 1; group 0 = P gather)
        ldw(W2g, W2s, 65536);                  // W2  (group 2)
#pragma unroll
        for (int kc = 0; kc < 2; kc++) { lda(Ain, 64, kc, av); sta(As + kc * CHUNKB, av); }
        asm volatile("cp.async.wait_group 1;" ::: "memory");   // P + W1b done
        __syncthreads();

#pragma unroll 1
        for (int nh = 0; nh < 2; nh++) {
            zacc(acc);
#pragma unroll
            for (int kc = 0; kc < 2; kc++)
                mma_chunk(acc, As + kc * CHUNKB + wm * 32 * ROWB, ROWB,
                          W1s + (size_t)(nh * 2 + kc) * CHUNKB);
            epilogue1(acc, nh);
        }
        asm volatile("cp.async.wait_group 0;" ::: "memory");   // W2 done
        __syncthreads();                                       // X1 published
    }

    // ================= MODE 2: node =================
    if constexpr (MODE == 2) {
        ldw(W1g, W1s, 65536);                  // W3 (group 0)
        ldw(W2g, W2s, 65536);                  // W4 (group 1)
        lda(Ain, 128, 0, av);
        sta(As, av);
        asm volatile("cp.async.wait_group 1;" ::: "memory");   // W3 done
        __syncthreads();

#pragma unroll 1
        for (int nh = 0; nh < 2; nh++) {
            zacc(acc);
#pragma unroll 1
            for (int kc = 0; kc < 4; kc++) {
                char* Acur = As + (kc & 1) * CHUNKB;
                if (kc + 1 < 4) lda(Ain, 128, kc + 1, av);
                mma_chunk(acc, Acur + wm * 32 * ROWB, ROWB,
                          W1s + (size_t)(nh * 4 + kc) * CHUNKB);
                if (kc + 1 < 4) sta(As + ((kc + 1) & 1) * CHUNKB, av);
                __syncthreads();
            }
            epilogue1(acc, nh);
            if (nh == 0) {                     // re-stage A chunk 0 for nh=1
                lda(Ain, 128, 0, av);
                __syncthreads();
                sta(As, av);
                __syncthreads();
            }
        }
        asm volatile("cp.async.wait_group 0;" ::: "memory");   // W4 done
        __syncthreads();                                       // X1 published
    }

    // ================= stage 2: Y = X1 @ W2 + b2 (K=256), barrier-free ========
    if constexpr (MODE != 0) {
        zacc(acc);
#pragma unroll
        for (int kc = 0; kc < 8; kc++)
            mma_chunk(acc, X1 + (size_t)(wm * 32) * XSTB + kc * 64, XSTB,
                      W2s + (size_t)kc * CHUNKB);

        float2 bv[4];
#pragma unroll
        for (int ni = 0; ni < 4; ni++)
            bv[ni] = *reinterpret_cast<const float2*>(b2 + wn * 32 + ni * 8 + 2 * t);

#pragma unroll
        for (int mi = 0; mi < 2; mi++)
#pragma unroll
            for (int half = 0; half < 2; half++) {
                const int row_l = wm * 32 + mi * 16 + g + half * 8;
                const int gm = m0 + row_l;
                if (gm < M) {
                    const size_t orow = EDGE ? (size_t)dstIdx[row_l] : (size_t)gm;
                    float* cp = Cout + orow * DIM + wn * 32 + 2 * t;
#pragma unroll
                    for (int ni = 0; ni < 4; ni++) {
                        float x = acc[mi][ni][half * 2 + 0] + bv[ni].x;
                        float y = acc[mi][ni][half * 2 + 1] + bv[ni].y;
                        if (EDGE) {
                            asm volatile("red.global.add.v2.f32 [%0], {%1, %2};"
                                         :: "l"(cp + ni * 8), "f"(x), "f"(y) : "memory");
                        } else {
                            *reinterpret_cast<float2*>(cp + ni * 8) = make_float2(x, y);
                        }
                    }
                }
            }
    }
}

// ===================== launch =====================
extern "C" void kernel_launch(void* const* d_in, const int* in_sizes, int n_in,
                              void* d_out, int out_size)
{
    const float* H         = (const float*)d_in[0];
    const int*   edge_idx  = (const int*)  d_in[1];
    const float* edge_attr = (const float*)d_in[2];
    const float* eps       = (const float*)d_in[3];
    const float* msg_W1    = (const float*)d_in[4];
    const float* msg_b1    = (const float*)d_in[5];
    const float* msg_W2    = (const float*)d_in[6];
    const float* msg_b2    = (const float*)d_in[7];
    const float* self_W1   = (const float*)d_in[8];
    const float* self_b1   = (const float*)d_in[9];
    const float* self_W2   = (const float*)d_in[10];
    const float* self_b2   = (const float*)d_in[11];

    const int* src = edge_idx;
    const int* dst = edge_idx + N_EDGES;
    float* out = (float*)d_out;

    float *agg;
    __half *P, *W1ap, *W1bp, *W2p, *W3p, *W4p;
    cudaGetSymbolAddress((void**)&agg,  g_agg);
    cudaGetSymbolAddress((void**)&P,    g_P);
    cudaGetSymbolAddress((void**)&W1ap, g_W1ap);
    cudaGetSymbolAddress((void**)&W1bp, g_W1bp);
    cudaGetSymbolAddress((void**)&W2p,  g_W2p);
    cudaGetSymbolAddress((void**)&W3p,  g_W3p);
    cudaGetSymbolAddress((void**)&W4p,  g_W4p);

    constexpr int SMEM_0 = 1024 + 4 * 8192 + 65536;                     //  99328
    constexpr int SMEM_1 = 1024 + 2 * 8192 + 32768 + 65536 + 128 * 576; // 189440
    constexpr int SMEM_2 = 1024 + 2 * 8192 + 65536 + 65536 + 128 * 576; // 222208

    cudaFuncSetAttribute((const void*)fused_mlp<0>,
                         cudaFuncAttributeMaxDynamicSharedMemorySize, SMEM_0);
    cudaFuncSetAttribute((const void*)fused_mlp<1>,
                         cudaFuncAttributeMaxDynamicSharedMemorySize, SMEM_1);
    cudaFuncSetAttribute((const void*)fused_mlp<2>,
                         cudaFuncAttributeMaxDynamicSharedMemorySize, SMEM_2);

    // 0) agg = (1+eps)*H
    init_agg_kernel<<<cdiv(N_NODES * DIM, 256), 256>>>(H, eps);
    // 1) all weights -> permuted fp16 (W1 split into W1a/W1b)
    cvt_all_kernel<<<cdiv(147456, 256), 256>>>(msg_W1, msg_W2, self_W1, self_W2,
                                               W1ap, W1bp, W2p, W3p, W4p);
    // 2) P = H @ W1a + b1 -> fp16 permuted rows   [N, 512B]
    fused_mlp<0><<<cdiv(N_NODES, 128), 512, SMEM_0>>>(
        H, W1ap, msg_b1, nullptr, nullptr, nullptr, (float*)P, nullptr, nullptr, N_NODES);
    // 3) edge: X1 = relu(P[src] + EA@W1b); agg[dst] += X1@W2 + b2   (ncu idx 3)
    fused_mlp<1><<<cdiv(N_EDGES, 128), 512, SMEM_1>>>(
        edge_attr, W1bp, nullptr, W2p, msg_b2, P, agg, src, dst, N_EDGES);
    // 4) node: out = MLP2(agg)
    fused_mlp<2><<<cdiv(N_NODES, 128), 512, SMEM_2>>>(
        agg, W3p, self_b1, W4p, self_b2, nullptr, out, nullptr, nullptr, N_NODES);
}

// round 17
// speedup vs baseline: 1.0722x; 1.0722x over previous
#include <cuda_runtime.h>
#include <cuda_fp16.h>
#include <cstdint>

// GINEdgeLayer via split-GEMM on fp16 mma.sync (m16n8k16, fp32 accum).
//   P = H@W1a + b1 per-node (fp16, X1-layout rows);
//   edge: X1 = relu(P[src] + EA@W1b); agg[dst] += X1@W2 + b2;
//   node: out = MLP2(agg).
//
// R16 = R15 (64-row CTA tile, 256 thr, 2 CTAs/SM) with the ring-schedule race
// fixed: the 2-slot rings never waited on the final chunk (c7) before its MMA.
// Added CPWAIT(0)+sync at i==6 / kc==6.
//
// Launch order (ncu capture = index 3 = fused edge kernel):
//   0: init_agg   1: cvt_all   2: P-gemm (MODE 0)   3: edge (MODE 1)   4: node (MODE 2)

static constexpr int N_NODES  = 20000;
static constexpr int N_EDGES  = 200000;
static constexpr int DIM      = 128;
static constexpr int EDGE_DIM = 64;
static constexpr int HID      = 256;

// ---- scratch (__device__ globals; no runtime allocation allowed) ----
__device__ float g_agg[(size_t)N_NODES * DIM];
__device__ __align__(16) __half g_P[(size_t)N_NODES * HID];   // 10.2 MB, permuted fp16
__device__ __align__(16) __half g_W1ap[8 * 128 * 32];  // [2nh*4kc][col][32] fp16 permuted
__device__ __align__(16) __half g_W1bp[4 * 128 * 32];  // [2nh*2kc][col][32]
__device__ __align__(16) __half g_W2p [8 * 128 * 32];  // [8kc][col][32]
__device__ __align__(16) __half g_W3p [8 * 128 * 32];
__device__ __align__(16) __half g_W4p [8 * 128 * 32];

static inline int cdiv(int a, int b) { return (a + b - 1) / b; }

__device__ __forceinline__ uint32_t smem_u32(const void* p) {
    uint32_t a;
    asm("{ .reg .u64 t; cvta.to.shared.u64 t, %1; cvt.u32.u64 %0, t; }" : "=r"(a) : "l"(p));
    return a;
}
// k-permutation for m16n8k16 fp16 fragments (one LDS.128 per row per 32-k chunk)
__device__ __forceinline__ int pos16(int w) {        // bijection on 0..31
    int s = w >> 4, r = w & 15;
    return ((r & 7) >> 1) * 8 + s * 4 + (r >> 3) * 2 + (r & 1);
}

__global__ __launch_bounds__(256)
void init_agg_kernel(const float* __restrict__ H, const float* __restrict__ eps) {
    int i = blockIdx.x * 256 + threadIdx.x;
    if (i < N_NODES * DIM) g_agg[i] = (1.0f + eps[0]) * H[i];
}

__device__ __forceinline__ void perm_write_h(const float* __restrict__ W,
                                             __half* __restrict__ P,
                                             int K, int N, int idx) {
    int k = idx / N, n = idx - k * N;
    int chunk = (n >> 7) * (K >> 5) + (k >> 5);
    P[(size_t)(chunk * 128 + (n & 127)) * 32 + pos16(k & 31)] = __float2half_rn(W[idx]);
}

__global__ __launch_bounds__(256)
void cvt_all_kernel(const float* __restrict__ mW1, const float* __restrict__ mW2,
                    const float* __restrict__ sW1, const float* __restrict__ sW2,
                    __half* __restrict__ W1ap, __half* __restrict__ W1bp,
                    __half* __restrict__ W2p,  __half* __restrict__ W3p,
                    __half* __restrict__ W4p) {
    int i = blockIdx.x * 256 + threadIdx.x;
    if (i < 32768)        perm_write_h(mW1, W1ap, 128, 256, i);
    else if (i < 49152) { // W1b: rows 128..191 of mW1, K=64, N=256
        int l = i - 32768;
        int k = l >> 8, n = l & 255;
        int chunk = (n >> 7) * 2 + (k >> 5);
        W1bp[(size_t)(chunk * 128 + (n & 127)) * 32 + pos16(k & 31)] =
            __float2half_rn(mW1[i]);
    }
    else if (i < 81920)   perm_write_h(mW2, W2p, 256, 128, i - 49152);
    else if (i < 114688)  perm_write_h(sW1, W3p, 128, 256, i - 81920);
    else if (i < 147456)  perm_write_h(sW2, W4p, 256, 128, i - 114688);
}

#define CP16(d, s) \
    asm volatile("cp.async.cg.shared.global [%0], [%1], 16;" :: "r"(d), "l"(s) : "memory")
#define CPCOMMIT()  asm volatile("cp.async.commit_group;" ::: "memory")
#define CPWAIT(n)   asm volatile("cp.async.wait_group %0;" :: "n"(n) : "memory")

// =====================================================================
// Unified kernel, CTA tile = 64 rows, 256 threads (8 warps, 2M x 4N,
// warp tile 32x32), fp16 MMA, fp32 accumulate. 2 CTAs/SM.
// MODE 0 (P):    P = H@W1a + b1 -> fp16 permuted rows [., 512B]
// MODE 1 (EDGE): X1 = relu(P[src] + EA@W1b); agg[dst] += X1@W2 + b2
// MODE 2 (NODE): out = MLP2(agg)
// =====================================================================
template<int MODE>
__global__ void __launch_bounds__(256, 2)
fused_mlp(const float* __restrict__ Ain,
          const __half* __restrict__ W1g, const float* __restrict__ b1,
          const __half* __restrict__ W2g, const float* __restrict__ b2,
          const __half* __restrict__ Pg,
          float*       __restrict__ Cout,
          const int*   __restrict__ srcv, const int* __restrict__ dstv,
          int M)
{
    constexpr bool EDGE = (MODE == 1);
    constexpr int  ROWB = 64;                  // A/B row stride bytes (32 halves)
    constexpr int  XSTB = 576;                 // X1 row stride bytes (conflict-free)
    constexpr int  ACH  = 64 * ROWB;           // A chunk: 4096 B (64 rows)
    constexpr int  BCH  = 128 * ROWB;          // B chunk: 8192 B (128 cols)
    constexpr int  NA   = (MODE == 1) ? 2 : 4; // resident A chunks
    constexpr int  OFF_A  = 1024;
    constexpr int  OFF_W1 = OFF_A + NA * ACH;
    constexpr int  W1SZ   = EDGE ? 4 * BCH : 2 * BCH;  // resident vs 2-ring
    constexpr int  OFF_W2 = OFF_W1 + W1SZ;
    constexpr int  W2SZ   = EDGE ? 4 * BCH : 2 * BCH;  // 4-ring vs 2-ring
    constexpr int  OFF_X  = OFF_W2 + ((MODE == 0) ? 0 : W2SZ);
    // MODE0: 33792   MODE1: 111616 (<=113664 -> 2 CTAs/SM)   MODE2: 87040

    extern __shared__ char smem[];
    int*  dstIdx = (int*)(smem + 512);
    char* As  = smem + OFF_A;
    char* W1s = smem + OFF_W1;
    char* W2s = smem + OFF_W2;
    char* X1  = smem + OFF_X;

    const int tid  = threadIdx.x;
    const int lane = tid & 31;
    const int g    = lane >> 2, t = lane & 3;
    const int wid  = tid >> 5;
    const int wm   = wid & 1, wn = wid >> 1;      // 2M x 4N warp grid
    const int m0   = blockIdx.x * 64;

    // ---- EDGE: gather P[src] rows (fp16 permuted, 512 B) into X1 smem ----
    if constexpr (EDGE) {
        int gr = m0 + (tid >> 2); if (gr >= M) gr = M - 1;
        int srow = srcv[gr];
        uint32_t xd = smem_u32(X1) + (uint32_t)(tid >> 2) * XSTB + (tid & 3) * 128;
        const char* ps = (const char*)Pg + (size_t)srow * 512 + (tid & 3) * 128;
#pragma unroll
        for (int j = 0; j < 8; j++) CP16(xd + j * 16, ps + j * 16);
        CPCOMMIT();                                     // group: P

        if (tid < 64) {
            int gm = m0 + tid;
            dstIdx[tid] = dstv[gm < M ? gm : M - 1];
        }
    }

    // ---- A staging: thread (row=tid/4, aq=tid&3), 8 consecutive k ----
    const int ar = tid >> 2, aq = tid & 3;
    int agm = m0 + ar; if (agm >= M) agm = M - 1;
    const int csub = (aq >> 1) * 2 + (aq & 1);

    auto lda = [&](const float* base, int K, int kc, float4* v) {
        const float* s = base + (size_t)agm * K + kc * 32 + aq * 8;
        v[0] = *reinterpret_cast<const float4*>(s);
        v[1] = *reinterpret_cast<const float4*>(s + 4);
    };
    auto sta = [&](char* buf, const float4* v) {  // fp16 permuted: 4x STS.32
        const float f[8] = { v[0].x, v[0].y, v[0].z, v[0].w,
                             v[1].x, v[1].y, v[1].z, v[1].w };
        uint32_t* d = (uint32_t*)(buf + ar * ROWB);
#pragma unroll
        for (int i = 0; i < 4; i++) {
            __half2 hh = __floats2half2_rn(f[2 * i], f[2 * i + 1]);
            d[i * 4 + csub] = *reinterpret_cast<uint32_t*>(&hh);
        }
    };

    // ---- bulk load of weight bytes into smem (one commit group) ----
    auto ldw = [&](const __half* srcW, char* dst, int bytes) {
        uint32_t d = smem_u32(dst);
        const char* s = (const char*)srcW;
#pragma unroll
        for (int off = tid * 16; off < bytes; off += 256 * 16)
            CP16(d + off, s + off);
        CPCOMMIT();
    };
    // one 8192-B weight chunk
    auto ldb = [&](const __half* srcW, int chunk, char* slot) {
        uint32_t d = smem_u32(slot);
        const char* s = (const char*)(srcW + (size_t)chunk * 4096);
        CP16(d + tid * 16, s + tid * 16);
        CP16(d + tid * 16 + 4096, s + tid * 16 + 4096);
        CPCOMMIT();
    };

    float acc[2][4][4];
    auto zacc = [&]() {
#pragma unroll
        for (int mi = 0; mi < 2; mi++)
#pragma unroll
            for (int ni = 0; ni < 4; ni++)
#pragma unroll
                for (int r = 0; r < 4; r++) acc[mi][ni][r] = 0.0f;
    };

    // fragment compute core: 12x LDS.128 + 16 MMA per warp per 32-k chunk
    auto mma_chunk = [&](const char* abase, int astB, const char* bbase) {
        uint4 a[2][2];
#pragma unroll
        for (int mi = 0; mi < 2; mi++)
#pragma unroll
            for (int rs = 0; rs < 2; rs++)
                a[mi][rs] = *reinterpret_cast<const uint4*>(
                    abase + (size_t)(mi * 16 + rs * 8 + g) * astB + t * 16);
        uint4 b[4];
#pragma unroll
        for (int ni = 0; ni < 4; ni++)
            b[ni] = *reinterpret_cast<const uint4*>(
                bbase + (size_t)(wn * 32 + ni * 8 + g) * ROWB + t * 16);
#pragma unroll
        for (int s = 0; s < 2; s++)
#pragma unroll
            for (int ni = 0; ni < 4; ni++) {
                uint32_t b0 = s ? b[ni].z : b[ni].x;
                uint32_t b1r = s ? b[ni].w : b[ni].y;
#pragma unroll
                for (int mi = 0; mi < 2; mi++) {
                    uint32_t a0 = s ? a[mi][0].z : a[mi][0].x;
                    uint32_t a1 = s ? a[mi][1].z : a[mi][1].x;
                    uint32_t a2 = s ? a[mi][0].w : a[mi][0].y;
                    uint32_t a3 = s ? a[mi][1].w : a[mi][1].y;
                    asm volatile(
                        "mma.sync.aligned.m16n8k16.row.col.f32.f16.f16.f32 "
                        "{%0,%1,%2,%3}, {%4,%5,%6,%7}, {%8,%9}, {%0,%1,%2,%3};"
                        : "+f"(acc[mi][ni][0]), "+f"(acc[mi][ni][1]),
                          "+f"(acc[mi][ni][2]), "+f"(acc[mi][ni][3])
                        : "r"(a0), "r"(a1), "r"(a2), "r"(a3), "r"(b0), "r"(b1r));
                }
            }
    };

    // ---- stage-1 epilogue (per N-half) ----
    auto epilogue1 = [&](int nh) {
        if constexpr (MODE == 0) {               // P: fp16 permuted rows to gmem
            float2 bv[4];
#pragma unroll
            for (int ni = 0; ni < 4; ni++)
                bv[ni] = *reinterpret_cast<const float2*>(b1 + nh * 128 + wn * 32 + ni * 8 + 2 * t);
#pragma unroll
            for (int mi = 0; mi < 2; mi++)
#pragma unroll
                for (int half = 0; half < 2; half++) {
                    const int row_l = wm * 32 + mi * 16 + g + half * 8;
                    const int gm = m0 + row_l;
                    if (gm < M) {
                        uint32_t pk[4];
#pragma unroll
                        for (int ni = 0; ni < 4; ni++) {
                            __half2 hh = __floats2half2_rn(
                                acc[mi][ni][half * 2 + 0] + bv[ni].x,
                                acc[mi][ni][half * 2 + 1] + bv[ni].y);
                            pk[ni] = *reinterpret_cast<uint32_t*>(&hh);
                        }
                        uint32_t* po = (uint32_t*)Cout + (size_t)gm * 128
                                     + (nh * 4 + wn) * 16 + t * 4;
                        *reinterpret_cast<uint4*>(po) =
                            make_uint4(pk[0], pk[1], pk[2], pk[3]);
                    }
                }
        } else {                                  // relu(P/bias + acc) -> X1 smem
            float2 bv[4];
            if (!EDGE) {
#pragma unroll
                for (int ni = 0; ni < 4; ni++)
                    bv[ni] = *reinterpret_cast<const float2*>(b1 + nh * 128 + wn * 32 + ni * 8 + 2 * t);
            }
#pragma unroll
            for (int mi = 0; mi < 2; mi++)
#pragma unroll
                for (int half = 0; half < 2; half++) {
                    const int row_l = wm * 32 + mi * 16 + g + half * 8;
                    uint32_t* xp = (uint32_t*)(X1 + (size_t)row_l * XSTB)
                                 + (nh * 4 + wn) * 16 + t * 4;
#pragma unroll
                    for (int ni = 0; ni < 4; ni++) {
                        float ax, ay;
                        if (EDGE) {               // gathered P already in X1 slot
                            uint32_t pv = xp[ni];
                            float2 pf = __half22float2(*reinterpret_cast<__half2*>(&pv));
                            ax = pf.x; ay = pf.y;
                        } else { ax = bv[ni].x; ay = bv[ni].y; }
                        float x = fmaxf(acc[mi][ni][half * 2 + 0] + ax, 0.0f);
                        float y = fmaxf(acc[mi][ni][half * 2 + 1] + ay, 0.0f);
                        __half2 hh = __floats2half2_rn(x, y);
                        xp[ni] = *reinterpret_cast<uint32_t*>(&hh);
                    }
                }
        }
    };

    float4 av[2];

    // ================= MODE 0: P-GEMM (W1a 2-ring, A resident) =================
    if constexpr (MODE == 0) {
        ldb(W1g, 0, W1s);                          // c0
        ldb(W1g, 1, W1s + BCH);                    // c1
#pragma unroll
        for (int kc = 0; kc < 4; kc++) { lda(Ain, 128, kc, av); sta(As + kc * ACH, av); }
        CPWAIT(1); __syncthreads();                // c0 + A published
        zacc();
#pragma unroll 1
        for (int i = 0; i < 8; i++) {              // i = nh*4 + kc
            mma_chunk(As + (i & 3) * ACH + wm * 32 * ROWB, ROWB, W1s + (i & 1) * BCH);
            if (i == 3) { epilogue1(0); zacc(); }
            else if (i == 7) { epilogue1(1); }
            if (i < 6) {
                __syncthreads();                   // slot (i&1) free
                ldb(W1g, i + 2, W1s + (i & 1) * BCH);
                CPWAIT(1);                         // c_{i+1} done (own portion)
                __syncthreads();                   // publish c_{i+1}
            } else if (i == 6) {
                CPWAIT(0);                         // FIX: c7 done (own portion)
                __syncthreads();                   // publish c7
            }
        }
        return;
    }

    // ================= MODE 1: edge =================
    if constexpr (MODE == 1) {
        ldw(W1g, W1s, 4 * BCH);                    // W1b resident
#pragma unroll
        for (int c = 0; c < 4; c++) ldb(W2g, c, W2s + c * BCH);  // W2 c0..c3
#pragma unroll
        for (int kc = 0; kc < 2; kc++) { lda(Ain, 64, kc, av); sta(As + kc * ACH, av); }
        CPWAIT(4); __syncthreads();                // P + W1b + A published

        // stage 1: fully resident, barrier-free
#pragma unroll 1
        for (int nh = 0; nh < 2; nh++) {
            zacc();
#pragma unroll
            for (int kc = 0; kc < 2; kc++)
                mma_chunk(As + kc * ACH + wm * 32 * ROWB, ROWB,
                          W1s + (size_t)(nh * 2 + kc) * BCH);
            epilogue1(nh);
        }
        CPWAIT(2); __syncthreads();                // W2 c0,c1 done; X1 published

        // stage 2: W2 4-slot ring, one barrier per chunk (shifted wait-publish)
        zacc();
#pragma unroll 1
        for (int kc = 0; kc < 8; kc++) {
            mma_chunk(X1 + (size_t)(wm * 32) * XSTB + kc * 64, XSTB,
                      W2s + (kc & 3) * BCH);
            if (kc < 4) {
                __syncthreads();                   // slot (kc&3) free
                ldb(W2g, kc + 4, W2s + (kc & 3) * BCH);
                CPWAIT(2);                         // chunk kc+2 done
            } else if (kc == 4) { __syncthreads(); CPWAIT(1); }   // pub c5; c6 done
            else if (kc == 5)   { __syncthreads(); CPWAIT(0); }   // pub c6; c7 done
            else if (kc == 6)   { __syncthreads(); }              // pub c7
        }
    }

    // ================= MODE 2: node (W3 2-ring, W4 2-ring, A resident) ========
    if constexpr (MODE == 2) {
        ldb(W1g, 0, W1s);                          // W3 c0
        ldb(W1g, 1, W1s + BCH);                    // W3 c1
#pragma unroll
        for (int kc = 0; kc < 4; kc++) { lda(Ain, 128, kc, av); sta(As + kc * ACH, av); }
        CPWAIT(1); __syncthreads();
        zacc();
#pragma unroll 1
        for (int i = 0; i < 8; i++) {
            mma_chunk(As + (i & 3) * ACH + wm * 32 * ROWB, ROWB, W1s + (i & 1) * BCH);
            if (i == 3) { epilogue1(0); zacc(); }
            else if (i == 7) { epilogue1(1); }
            if (i < 6) {
                __syncthreads();
                ldb(W1g, i + 2, W1s + (i & 1) * BCH);
                CPWAIT(1);
                __syncthreads();
            } else if (i == 6) {
                CPWAIT(0);                         // FIX: c7 done (own portion)
                __syncthreads();                   // publish c7
            }
        }
        ldb(W2g, 0, W2s);                          // W4 c0
        ldb(W2g, 1, W2s + BCH);                    // W4 c1
        CPWAIT(1); __syncthreads();                // W4 c0 + X1 published

        zacc();
#pragma unroll 1
        for (int kc = 0; kc < 8; kc++) {
            mma_chunk(X1 + (size_t)(wm * 32) * XSTB + kc * 64, XSTB,
                      W2s + (kc & 1) * BCH);
            if (kc < 6) {
                __syncthreads();
                ldb(W2g, kc + 2, W2s + (kc & 1) * BCH);
                CPWAIT(1);
                __syncthreads();
            } else if (kc == 6) {
                CPWAIT(0);                         // FIX: c7 done (own portion)
                __syncthreads();                   // publish c7
            }
        }
    }

    // ================= stage-2 epilogue (EDGE scatter / NODE store) ===========
    if constexpr (MODE != 0) {
        float2 bv[4];
#pragma unroll
        for (int ni = 0; ni < 4; ni++)
            bv[ni] = *reinterpret_cast<const float2*>(b2 + wn * 32 + ni * 8 + 2 * t);

#pragma unroll
        for (int mi = 0; mi < 2; mi++)
#pragma unroll
            for (int half = 0; half < 2; half++) {
                const int row_l = wm * 32 + mi * 16 + g + half * 8;
                const int gm = m0 + row_l;
                if (gm < M) {
                    const size_t orow = EDGE ? (size_t)dstIdx[row_l] : (size_t)gm;
                    float* cp = Cout + orow * DIM + wn * 32 + 2 * t;
#pragma unroll
                    for (int ni = 0; ni < 4; ni++) {
                        float x = acc[mi][ni][half * 2 + 0] + bv[ni].x;
                        float y = acc[mi][ni][half * 2 + 1] + bv[ni].y;
                        if (EDGE) {
                            asm volatile("red.global.add.v2.f32 [%0], {%1, %2};"
                                         :: "l"(cp + ni * 8), "f"(x), "f"(y) : "memory");
                        } else {
                            *reinterpret_cast<float2*>(cp + ni * 8) = make_float2(x, y);
                        }
                    }
                }
            }
    }
}

// ===================== launch =====================
extern "C" void kernel_launch(void* const* d_in, const int* in_sizes, int n_in,
                              void* d_out, int out_size)
{
    const float* H         = (const float*)d_in[0];
    const int*   edge_idx  = (const int*)  d_in[1];
    const float* edge_attr = (const float*)d_in[2];
    const float* eps       = (const float*)d_in[3];
    const float* msg_W1    = (const float*)d_in[4];
    const float* msg_b1    = (const float*)d_in[5];
    const float* msg_W2    = (const float*)d_in[6];
    const float* msg_b2    = (const float*)d_in[7];
    const float* self_W1   = (const float*)d_in[8];
    const float* self_b1   = (const float*)d_in[9];
    const float* self_W2   = (const float*)d_in[10];
    const float* self_b2   = (const float*)d_in[11];

    const int* src = edge_idx;
    const int* dst = edge_idx + N_EDGES;
    float* out = (float*)d_out;

    float *agg;
    __half *P, *W1ap, *W1bp, *W2p, *W3p, *W4p;
    cudaGetSymbolAddress((void**)&agg,  g_agg);
    cudaGetSymbolAddress((void**)&P,    g_P);
    cudaGetSymbolAddress((void**)&W1ap, g_W1ap);
    cudaGetSymbolAddress((void**)&W1bp, g_W1bp);
    cudaGetSymbolAddress((void**)&W2p,  g_W2p);
    cudaGetSymbolAddress((void**)&W3p,  g_W3p);
    cudaGetSymbolAddress((void**)&W4p,  g_W4p);

    constexpr int SMEM_0 = 1024 + 4 * 4096 + 2 * 8192;                        //  33792
    constexpr int SMEM_1 = 1024 + 2 * 4096 + 4 * 8192 + 4 * 8192 + 64 * 576;  // 111616
    constexpr int SMEM_2 = 1024 + 4 * 4096 + 2 * 8192 + 2 * 8192 + 64 * 576;  //  87040

    cudaFuncSetAttribute((const void*)fused_mlp<0>,
                         cudaFuncAttributeMaxDynamicSharedMemorySize, SMEM_0);
    cudaFuncSetAttribute((const void*)fused_mlp<1>,
                         cudaFuncAttributeMaxDynamicSharedMemorySize, SMEM_1);
    cudaFuncSetAttribute((const void*)fused_mlp<2>,
                         cudaFuncAttributeMaxDynamicSharedMemorySize, SMEM_2);

    // 0) agg = (1+eps)*H
    init_agg_kernel<<<cdiv(N_NODES * DIM, 256), 256>>>(H, eps);
    // 1) all weights -> permuted fp16 (W1 split into W1a/W1b)
    cvt_all_kernel<<<cdiv(147456, 256), 256>>>(msg_W1, msg_W2, self_W1, self_W2,
                                               W1ap, W1bp, W2p, W3p, W4p);
    // 2) P = H @ W1a + b1 -> fp16 permuted rows   [N, 512B]
    fused_mlp<0><<<cdiv(N_NODES, 64), 256, SMEM_0>>>(
        H, W1ap, msg_b1, nullptr, nullptr, nullptr, (float*)P, nullptr, nullptr, N_NODES);
    // 3) edge: X1 = relu(P[src] + EA@W1b); agg[dst] += X1@W2 + b2   (ncu idx 3)
    fused_mlp<1><<<cdiv(N_EDGES, 64), 256, SMEM_1>>>(
        edge_attr, W1bp, nullptr, W2p, msg_b2, P, agg, src, dst, N_EDGES);
    // 4) node: out = MLP2(agg)
    fused_mlp<2><<<cdiv(N_NODES, 64), 256, SMEM_2>>>(
        agg, W3p, self_b1, W4p, self_b2, nullptr, out, nullptr, nullptr, N_NODES);
}